// round 1
// baseline (speedup 1.0000x reference)
#include <cuda_runtime.h>
#include <cuda_bf16.h>

#define B    4
#define NB   131072
#define K    32
#define NTOT (B*NB)
#define HALF 384.0f

#define THREADS1      256
#define GP            4
#define PTS_PER_BLOCK (THREADS1*GP)           // 1024
#define NBLOCKS       (NTOT/PTS_PER_BLOCK)    // 512
#define BPB_SHIFT     7                        // 128 blocks per batch

// ---- persistent device scratch (no allocations allowed) ----
// accumulator layout inside g_accum:
#define A_SUM    0      // 512 floats: [(b*K+k)*4 + c], c=0..2 ce sums, c=3 sigma sum
#define A_CNT    512    // 128
#define A_SMOOTH 640    // 128
#define A_SEED   768    // 128
#define A_MASK   896    // 4
#define A_ACC    900    // 1
#define A_TOTAL  901

__device__ float  g_accum[A_TOTAL];
__device__ float4 g_ck[B*K];    // cx, cy, cz, 1/(2*sigma^2)
__device__ float  g_sig[B*K];
__device__ float  g_cnt[B*K];

__global__ void k_zero() {
    int i = blockIdx.x * blockDim.x + threadIdx.x;
    if (i < A_TOTAL) g_accum[i] = 0.f;
}

// ---- pass 1: per-(batch,cluster) sums of ce, sigma, count ----
__global__ void k_pass1(const float4* __restrict__ emb, const float* __restrict__ lab) {
    __shared__ float s[K * 5];
    int tid = threadIdx.x;
    if (tid < K * 5) s[tid] = 0.f;
    __syncthreads();

    int base = blockIdx.x * PTS_PER_BLOCK;
    #pragma unroll
    for (int g = 0; g < GP; g++) {
        int n = base + tid + g * THREADS1;
        float4 e = emb[n];
        const float* L = lab + (size_t)n * 6;
        float ce0 = e.x + (L[1] - HALF) * (1.f / HALF);
        float ce1 = e.y + (L[2] - HALF) * (1.f / HALF);
        float ce2 = e.z + (L[3] - HALF) * (1.f / HALF);
        int inst = (int)L[5];
        inst = max(0, min(K - 1, inst));
        float* sk = s + inst * 5;
        atomicAdd(sk + 0, ce0);
        atomicAdd(sk + 1, ce1);
        atomicAdd(sk + 2, ce2);
        atomicAdd(sk + 3, e.w);
        atomicAdd(sk + 4, 1.f);
    }
    __syncthreads();

    int b = blockIdx.x >> BPB_SHIFT;
    if (tid < K * 5) {
        int k = tid / 5, c = tid % 5;
        float v = s[tid];
        if (c < 4) atomicAdd(&g_accum[A_SUM + (b * K + k) * 4 + c], v);
        else       atomicAdd(&g_accum[A_CNT + b * K + k], v);
    }
}

// ---- pass 2: finalize centers / sigmas / counts ----
__global__ void k_pass2() {
    int t = threadIdx.x;     // 128 = B*K
    float cnt = fmaxf(g_accum[A_CNT + t], 1.f);
    float inv = 1.f / cnt;
    float cx = g_accum[A_SUM + t * 4 + 0] * inv;
    float cy = g_accum[A_SUM + t * 4 + 1] * inv;
    float cz = g_accum[A_SUM + t * 4 + 2] * inv;
    float sg = g_accum[A_SUM + t * 4 + 3] * inv;
    g_ck[t]  = make_float4(cx, cy, cz, 1.f / (2.f * sg * sg));
    g_sig[t] = sg;
    g_cnt[t] = cnt;
}

// ---- pass 3: main N x K loop ----
__global__ void k_pass3(const float4* __restrict__ emb,
                        const float*  __restrict__ seedp,
                        const float*  __restrict__ lab) {
    __shared__ float4 sck[K];
    __shared__ float  ssig[K], ssm[K], ssd[K];
    __shared__ float  smask, sacc;
    int tid = threadIdx.x;
    int b = blockIdx.x >> BPB_SHIFT;
    if (tid < K) {
        sck[tid]  = g_ck[b * K + tid];
        ssig[tid] = g_sig[b * K + tid];
        ssm[tid] = 0.f;
        ssd[tid] = 0.f;
    }
    if (tid == 0) { smask = 0.f; sacc = 0.f; }
    __syncthreads();

    int base = blockIdx.x * PTS_PER_BLOCK;
    float mloc = 0.f, aloc = 0.f;
    #pragma unroll 1
    for (int g = 0; g < GP; g++) {
        int n = base + tid + g * THREADS1;
        float4 e = emb[n];
        const float* L = lab + (size_t)n * 6;
        float ce0 = e.x + (L[1] - HALF) * (1.f / HALF);
        float ce1 = e.y + (L[2] - HALF) * (1.f / HALF);
        float ce2 = e.z + (L[3] - HALF) * (1.f / HALF);
        int inst = (int)L[5];
        inst = max(0, min(K - 1, inst));
        float seed = seedp[n];

        float best = 3.4e38f;
        int   bi   = 0;
        float m    = 0.f;
        float argi = 100.f;
        #pragma unroll
        for (int k = 0; k < K; k++) {
            float4 c = sck[k];
            float d0 = ce0 - c.x, d1 = ce1 - c.y, d2 = ce2 - c.z;
            float dist2 = fmaf(d0, d0, fmaf(d1, d1, d2 * d2));
            if (dist2 < best) { best = dist2; bi = k; }
            float arg = fminf(fmaxf(dist2 * c.w, 1e-7f), 100.f);
            if (k == inst) {
                m += arg;
                argi = arg;
            } else if (arg < 87.f) {
                // -log1p(-exp(-arg)); below fp32 this path == reference exactly
                float omp;
                if (arg < 0.0625f) {
                    // 1-exp(-a) = a*(1 - a/2 + a^2/6), rel err < 1e-5 for a<1/16
                    omp = arg * (1.f + arg * (-0.5f + arg * (1.f / 6.f)));
                } else {
                    omp = 1.f - __expf(-arg);
                }
                m -= __logf(omp);
            }
            // arg >= 87 (non-inst): term <= 1.6e-38, a no-op in fp32 accumulation
        }
        float pi = __expf(-argi);
        float ds = seed - pi;
        atomicAdd(&ssm[inst], fabsf(e.w - ssig[inst]));
        atomicAdd(&ssd[inst], ds * ds);
        mloc += m;
        aloc += (bi == inst) ? 1.f : 0.f;
    }
    atomicAdd(&smask, mloc);
    atomicAdd(&sacc, aloc);
    __syncthreads();

    if (tid < K) {
        atomicAdd(&g_accum[A_SMOOTH + b * K + tid], ssm[tid]);
        atomicAdd(&g_accum[A_SEED   + b * K + tid], ssd[tid]);
    }
    if (tid == 0) {
        atomicAdd(&g_accum[A_MASK + b], smask);
        atomicAdd(&g_accum[A_ACC], sacc);
    }
}

// ---- pass 4: inter-cluster hinge + final combine ----
__global__ void k_pass4(float* __restrict__ out, int out_size) {
    __shared__ float sv[B * K];
    __shared__ float sb[B];
    int t = threadIdx.x;          // 128 = B*K
    int b = t >> 5, k = t & 31;

    float4 ck = g_ck[t];
    float hs = 0.f;
    #pragma unroll
    for (int j = 0; j < K; j++) {
        if (j == k) continue;
        float4 cj = g_ck[b * K + j];
        float d0 = ck.x - cj.x, d1 = ck.y - cj.y, d2 = ck.z - cj.z;
        float cd2 = fmaf(d0, d0, fmaf(d1, d1, d2 * d2));
        float d = sqrtf(cd2);
        float h = fmaxf(0.f, 1.f - d);
        hs += h * h;
    }
    float cnt = g_cnt[t];
    float val = (g_accum[A_SMOOTH + t] + g_accum[A_SEED + t]) / cnt * (1.f / (float)K)
              + hs * (1.f / (2.f * (float)K * (float)(K - 1)));
    sv[t] = val;
    __syncthreads();
    if (k == 0) {
        float s = 0.f;
        for (int j = 0; j < K; j++) s += sv[b * K + j];
        s += g_accum[A_MASK + b] * (1.f / ((float)NB * (float)K));
        sb[b] = s;
    }
    __syncthreads();
    if (t == 0) {
        float loss = 0.25f * (sb[0] + sb[1] + sb[2] + sb[3]);
        out[0] = loss;
        if (out_size > 1) out[1] = g_accum[A_ACC] * (1.f / (float)NTOT);
    }
}

extern "C" void kernel_launch(void* const* d_in, const int* in_sizes, int n_in,
                              void* d_out, int out_size) {
    const float4* emb  = (const float4*)d_in[0];
    const float*  seed = (const float*)d_in[1];
    const float*  lab  = (const float*)d_in[2];
    float* out = (float*)d_out;

    k_zero <<<1, 1024>>>();
    k_pass1<<<NBLOCKS, THREADS1>>>(emb, lab);
    k_pass2<<<1, B * K>>>();
    k_pass3<<<NBLOCKS, THREADS1>>>(emb, seed, lab);
    k_pass4<<<1, B * K>>>(out, out_size);
}